// round 1
// baseline (speedup 1.0000x reference)
#include <cuda_runtime.h>
#include <stdint.h>

#define B_ 4
#define S_ 2048
#define D_ 1024
#define H_ 16
#define DK_ 64

// Scratch (device globals: allocation-free rule)
__device__ float g_Q[B_*S_*D_];
__device__ float g_K[B_*S_*D_];
__device__ float g_V[B_*S_*D_];
__device__ float g_A[B_*S_*D_];

__device__ __forceinline__ uint32_t f2tf(float f){
  uint32_t o; asm("cvt.rna.tf32.f32 %0, %1;" : "=r"(o) : "f"(f)); return o;
}

__device__ __forceinline__ void mma_tf32(float* c, const uint32_t* a, uint32_t b0, uint32_t b1){
  asm volatile("mma.sync.aligned.m16n8k8.row.col.f32.tf32.tf32.f32 "
    "{%0,%1,%2,%3},{%4,%5,%6,%7},{%8,%9},{%0,%1,%2,%3};"
    : "+f"(c[0]),"+f"(c[1]),"+f"(c[2]),"+f"(c[3])
    : "r"(a[0]),"r"(a[1]),"r"(a[2]),"r"(a[3]),"r"(b0),"r"(b1));
}

// ---------------------------------------------------------------------------
// GEMM: Y[M,N] = X[M,K] @ W[N,K]^T + bias[N]   (torch Linear semantics)
// 128x128x32 tiles, 256 threads, warp grid 2x4 (warp tile 64x32), tf32 MMA.
// ---------------------------------------------------------------------------
__global__ __launch_bounds__(256,1)
void gemm_tf32(const float* __restrict__ X, const float* __restrict__ W,
               const float* __restrict__ bias, float* __restrict__ Y,
               int M, int N, int K) {
  __shared__ uint32_t As[128*36];
  __shared__ uint32_t Bs[128*36];
  const int tid  = threadIdx.x;
  const int warp = tid >> 5, lane = tid & 31;
  const int wm = warp >> 2, wn = warp & 3;
  const int g = lane >> 2, q = lane & 3;
  const int bm = blockIdx.y * 128, bn = blockIdx.x * 128;
  const int lrow = tid >> 3, lcol = (tid & 7) * 4;

  const float* Xp = X + (bm + lrow) * K + lcol;
  const float* Wp = W + (bn + lrow) * K + lcol;

  float acc[4][4][4];
  #pragma unroll
  for (int i=0;i<4;i++)
    #pragma unroll
    for (int j=0;j<4;j++)
      #pragma unroll
      for (int r=0;r<4;r++) acc[i][j][r]=0.f;

  float4 ra[4], rb[4];
  #pragma unroll
  for (int i=0;i<4;i++){
    ra[i] = *(const float4*)(Xp + (32*i)*K);
    rb[i] = *(const float4*)(Wp + (32*i)*K);
  }

  const int KT = K / 32;
  for (int kt=0; kt<KT; kt++){
    #pragma unroll
    for (int i=0;i<4;i++){
      uint4 av = make_uint4(f2tf(ra[i].x),f2tf(ra[i].y),f2tf(ra[i].z),f2tf(ra[i].w));
      uint4 bv = make_uint4(f2tf(rb[i].x),f2tf(rb[i].y),f2tf(rb[i].z),f2tf(rb[i].w));
      *(uint4*)&As[(lrow+32*i)*36 + lcol] = av;
      *(uint4*)&Bs[(lrow+32*i)*36 + lcol] = bv;
    }
    __syncthreads();
    if (kt+1 < KT){
      #pragma unroll
      for (int i=0;i<4;i++){
        ra[i] = *(const float4*)(Xp + (kt+1)*32 + (32*i)*K);
        rb[i] = *(const float4*)(Wp + (kt+1)*32 + (32*i)*K);
      }
    }
    #pragma unroll
    for (int ks=0; ks<4; ks++){
      const int kk = ks*8 + q;
      uint32_t af[4][4];
      #pragma unroll
      for (int mt=0; mt<4; mt++){
        const int row = wm*64 + mt*16 + g;
        af[mt][0] = As[row*36 + kk];
        af[mt][1] = As[(row+8)*36 + kk];
        af[mt][2] = As[row*36 + kk+4];
        af[mt][3] = As[(row+8)*36 + kk+4];
      }
      #pragma unroll
      for (int nt=0; nt<4; nt++){
        const int nn = wn*32 + nt*8 + g;
        const uint32_t b0 = Bs[nn*36 + kk];
        const uint32_t b1 = Bs[nn*36 + kk+4];
        #pragma unroll
        for (int mt=0; mt<4; mt++)
          mma_tf32(acc[mt][nt], af[mt], b0, b1);
      }
    }
    __syncthreads();
  }

  #pragma unroll
  for (int mt=0; mt<4; mt++){
    const int r0 = bm + wm*64 + mt*16 + g;
    #pragma unroll
    for (int nt=0; nt<4; nt++){
      const int c = bn + wn*32 + nt*8 + 2*q;
      const float b0 = bias[c], b1 = bias[c+1];
      *(float2*)&Y[r0*N + c]     = make_float2(acc[mt][nt][0]+b0, acc[mt][nt][1]+b1);
      *(float2*)&Y[(r0+8)*N + c] = make_float2(acc[mt][nt][2]+b0, acc[mt][nt][3]+b1);
    }
  }
}

// ---------------------------------------------------------------------------
// Causal flash attention, tf32 MMA. One block per (q-tile of 128, b*h).
// 8 warps; each warp owns 16 query rows (softmax stays in-warp).
// ---------------------------------------------------------------------------
#define KS_STRIDE 68
#define VS_STRIDE 72
#define PS_STRIDE 132
#define SMEM_ATT ((128*KS_STRIDE + 128*VS_STRIDE + 128*PS_STRIDE)*4)

__global__ __launch_bounds__(256,1)
void attn_tf32(const float* __restrict__ Q, const float* __restrict__ K,
               const float* __restrict__ V, float* __restrict__ O) {
  extern __shared__ uint32_t sm[];
  uint32_t* Ks = sm;
  uint32_t* Vs = sm + 128*KS_STRIDE;
  uint32_t* Ps = Vs + 128*VS_STRIDE;

  const int tid = threadIdx.x, warp = tid >> 5, lane = tid & 31;
  const int g = lane >> 2, q = lane & 3;
  const int iq = blockIdx.x, bh = blockIdx.y;
  const int b = bh >> 4, h = bh & 15;
  const int base = b * S_ * D_;
  const int hcol = h * DK_;
  const int qb = iq * 128;

  // persistent Q fragments (m16 x k64 per warp)
  uint32_t qf[8][4];
  {
    const float* q0 = Q + base + (qb + warp*16 + g)*D_ + hcol;
    const float* q1 = q0 + 8*D_;
    #pragma unroll
    for (int kt=0; kt<8; kt++){
      qf[kt][0] = f2tf(q0[kt*8+q]);
      qf[kt][1] = f2tf(q1[kt*8+q]);
      qf[kt][2] = f2tf(q0[kt*8+q+4]);
      qf[kt][3] = f2tf(q1[kt*8+q+4]);
    }
  }

  float oacc[8][4];
  #pragma unroll
  for (int i=0;i<8;i++){ oacc[i][0]=0.f; oacc[i][1]=0.f; oacc[i][2]=0.f; oacc[i][3]=0.f; }
  float m0=-1e30f, m1=-1e30f, l0=0.f, l1=0.f;
  const float SC = 0.1803368801111204f;  // log2(e) / sqrt(64)

  const int lr = tid >> 4, lc = (tid & 15) * 4;
  const int row0 = qb + warp*16 + g;
  const int row1 = row0 + 8;
  uint32_t* pw = Ps + warp*16*PS_STRIDE;   // warp-private P rows

  for (int j=0; j<=iq; j++){
    __syncthreads();               // prior iter done reading Ks/Vs
    const int kb = j*128;
    #pragma unroll
    for (int i=0;i<8;i++){
      const int r = lr + 16*i;
      const float4 kx = *(const float4*)(K + base + (kb+r)*D_ + hcol + lc);
      const float4 vx = *(const float4*)(V + base + (kb+r)*D_ + hcol + lc);
      *(uint4*)&Ks[r*KS_STRIDE + lc] = make_uint4(f2tf(kx.x),f2tf(kx.y),f2tf(kx.z),f2tf(kx.w));
      *(uint4*)&Vs[r*VS_STRIDE + lc] = make_uint4(f2tf(vx.x),f2tf(vx.y),f2tf(vx.z),f2tf(vx.w));
    }
    __syncthreads();

    // S = Q @ K^T  (m16 x n128 per warp)
    float s[16][4];
    #pragma unroll
    for (int nt=0;nt<16;nt++){ s[nt][0]=0.f; s[nt][1]=0.f; s[nt][2]=0.f; s[nt][3]=0.f; }
    #pragma unroll
    for (int kt=0; kt<8; kt++){
      #pragma unroll
      for (int nt=0; nt<16; nt++){
        const uint32_t b0 = Ks[(nt*8+g)*KS_STRIDE + kt*8+q];
        const uint32_t b1 = Ks[(nt*8+g)*KS_STRIDE + kt*8+q+4];
        mma_tf32(s[nt], qf[kt], b0, b1);
      }
    }

    // scale + causal mask (only the diagonal tile needs masking) + row max
    const bool diag = (j == iq);
    float mx0=-1e30f, mx1=-1e30f;
    #pragma unroll
    for (int nt=0; nt<16; nt++){
      const int c0 = kb + nt*8 + 2*q;
      float v0 = s[nt][0]*SC, v1 = s[nt][1]*SC, v2 = s[nt][2]*SC, v3 = s[nt][3]*SC;
      if (diag){
        if (c0   > row0) v0 = -1e30f;
        if (c0+1 > row0) v1 = -1e30f;
        if (c0   > row1) v2 = -1e30f;
        if (c0+1 > row1) v3 = -1e30f;
      }
      s[nt][0]=v0; s[nt][1]=v1; s[nt][2]=v2; s[nt][3]=v3;
      mx0 = fmaxf(mx0, fmaxf(v0,v1));
      mx1 = fmaxf(mx1, fmaxf(v2,v3));
    }
    mx0 = fmaxf(mx0, __shfl_xor_sync(0xffffffffu, mx0, 1));
    mx0 = fmaxf(mx0, __shfl_xor_sync(0xffffffffu, mx0, 2));
    mx1 = fmaxf(mx1, __shfl_xor_sync(0xffffffffu, mx1, 1));
    mx1 = fmaxf(mx1, __shfl_xor_sync(0xffffffffu, mx1, 2));
    const float mn0 = fmaxf(m0, mx0), mn1 = fmaxf(m1, mx1);
    const float a0 = exp2f(m0 - mn0), a1 = exp2f(m1 - mn1);
    m0 = mn0; m1 = mn1;

    float sum0=0.f, sum1=0.f;
    #pragma unroll
    for (int nt=0; nt<16; nt++){
      const float p0 = exp2f(s[nt][0]-m0);
      const float p1 = exp2f(s[nt][1]-m0);
      const float p2 = exp2f(s[nt][2]-m1);
      const float p3 = exp2f(s[nt][3]-m1);
      sum0 += p0+p1; sum1 += p2+p3;
      pw[g*PS_STRIDE     + nt*8 + 2*q]   = f2tf(p0);
      pw[g*PS_STRIDE     + nt*8 + 2*q+1] = f2tf(p1);
      pw[(g+8)*PS_STRIDE + nt*8 + 2*q]   = f2tf(p2);
      pw[(g+8)*PS_STRIDE + nt*8 + 2*q+1] = f2tf(p3);
    }
    sum0 += __shfl_xor_sync(0xffffffffu, sum0, 1);
    sum0 += __shfl_xor_sync(0xffffffffu, sum0, 2);
    sum1 += __shfl_xor_sync(0xffffffffu, sum1, 1);
    sum1 += __shfl_xor_sync(0xffffffffu, sum1, 2);
    l0 = l0*a0 + sum0; l1 = l1*a1 + sum1;
    #pragma unroll
    for (int nt=0; nt<8; nt++){
      oacc[nt][0]*=a0; oacc[nt][1]*=a0; oacc[nt][2]*=a1; oacc[nt][3]*=a1;
    }
    __syncwarp();   // P visible to whole warp

    // O += P @ V  (k = 128, n = 64)
    #pragma unroll
    for (int kt=0; kt<16; kt++){
      uint32_t pa[4];
      pa[0] = pw[g*PS_STRIDE     + kt*8 + q];
      pa[1] = pw[(g+8)*PS_STRIDE + kt*8 + q];
      pa[2] = pw[g*PS_STRIDE     + kt*8 + q + 4];
      pa[3] = pw[(g+8)*PS_STRIDE + kt*8 + q + 4];
      #pragma unroll
      for (int nt=0; nt<8; nt++){
        const uint32_t b0v = Vs[(kt*8+q)*VS_STRIDE   + nt*8 + g];
        const uint32_t b1v = Vs[(kt*8+q+4)*VS_STRIDE + nt*8 + g];
        mma_tf32(oacc[nt], pa, b0v, b1v);
      }
    }
  }

  const float i0 = 1.f/l0, i1 = 1.f/l1;
  float* o0 = O + base + row0*D_ + hcol;
  float* o1 = O + base + row1*D_ + hcol;
  #pragma unroll
  for (int nt=0; nt<8; nt++){
    const int c = nt*8 + 2*q;
    *(float2*)&o0[c] = make_float2(oacc[nt][0]*i0, oacc[nt][1]*i0);
    *(float2*)&o1[c] = make_float2(oacc[nt][2]*i1, oacc[nt][3]*i1);
  }
}

// ---------------------------------------------------------------------------
extern "C" void kernel_launch(void* const* d_in, const int* in_sizes, int n_in,
                              void* d_out, int out_size){
  const float* xq = (const float*)d_in[0];
  const float* xk = (const float*)d_in[1];
  const float* xv = (const float*)d_in[2];
  const float* Wq = (const float*)d_in[3];
  const float* bq = (const float*)d_in[4];
  const float* Wk = (const float*)d_in[5];
  const float* bk = (const float*)d_in[6];
  const float* Wv = (const float*)d_in[7];
  const float* bv = (const float*)d_in[8];
  const float* Wo = (const float*)d_in[9];
  const float* bo = (const float*)d_in[10];
  // d_in[11] = causal_mask (unused; causality computed analytically)
  float* out = (float*)d_out;

  float *gq, *gk, *gv, *ga;
  cudaGetSymbolAddress((void**)&gq, g_Q);
  cudaGetSymbolAddress((void**)&gk, g_K);
  cudaGetSymbolAddress((void**)&gv, g_V);
  cudaGetSymbolAddress((void**)&ga, g_A);

  cudaFuncSetAttribute(attn_tf32, cudaFuncAttributeMaxDynamicSharedMemorySize, SMEM_ATT);

  const int M = B_ * S_;
  dim3 gg(D_/128, M/128);
  gemm_tf32<<<gg, 256>>>(xq, Wq, bq, gq, M, D_, D_);
  gemm_tf32<<<gg, 256>>>(xk, Wk, bk, gk, M, D_, D_);
  gemm_tf32<<<gg, 256>>>(xv, Wv, bv, gv, M, D_, D_);
  attn_tf32<<<dim3(16, B_*H_), 256, SMEM_ATT>>>(gq, gk, gv, ga);
  gemm_tf32<<<gg, 256>>>(ga, Wo, bo, out, M, D_, D_);
}

// round 2
// speedup vs baseline: 2.2408x; 2.2408x over previous
#include <cuda_runtime.h>
#include <cuda_fp16.h>
#include <stdint.h>

#define B_ 4
#define S_ 2048
#define D_ 1024
#define H_ 16
#define DK_ 64
#define MTOT (B_*S_)

// fp16 staging buffers (device globals: allocation-free rule)
__device__ __half g_xq[MTOT*D_];
__device__ __half g_xk[MTOT*D_];
__device__ __half g_xv[MTOT*D_];
__device__ __half g_wq[D_*D_];
__device__ __half g_wk[D_*D_];
__device__ __half g_wv[D_*D_];
__device__ __half g_wo[D_*D_];
__device__ __half g_Q[MTOT*D_];
__device__ __half g_K[MTOT*D_];
__device__ __half g_V[MTOT*D_];
__device__ __half g_A[MTOT*D_];

// ---------------- PTX helpers ----------------
__device__ __forceinline__ void ldsm4(uint32_t* r, uint32_t a){
  asm volatile("ldmatrix.sync.aligned.m8n8.x4.shared.b16 {%0,%1,%2,%3},[%4];"
    : "=r"(r[0]),"=r"(r[1]),"=r"(r[2]),"=r"(r[3]) : "r"(a));
}
__device__ __forceinline__ void ldsm4t(uint32_t* r, uint32_t a){
  asm volatile("ldmatrix.sync.aligned.m8n8.x4.trans.shared.b16 {%0,%1,%2,%3},[%4];"
    : "=r"(r[0]),"=r"(r[1]),"=r"(r[2]),"=r"(r[3]) : "r"(a));
}
__device__ __forceinline__ void mma16816(float* c, const uint32_t* a, uint32_t b0, uint32_t b1){
  asm volatile("mma.sync.aligned.m16n8k16.row.col.f32.f16.f16.f32 "
    "{%0,%1,%2,%3},{%4,%5,%6,%7},{%8,%9},{%0,%1,%2,%3};"
    : "+f"(c[0]),"+f"(c[1]),"+f"(c[2]),"+f"(c[3])
    : "r"(a[0]),"r"(a[1]),"r"(a[2]),"r"(a[3]),"r"(b0),"r"(b1));
}
__device__ __forceinline__ void cp16(uint32_t d, const void* s){
  asm volatile("cp.async.cg.shared.global [%0],[%1],16;" :: "r"(d),"l"(s));
}
#define CP_COMMIT() asm volatile("cp.async.commit_group;")
#define CP_WAIT0()  asm volatile("cp.async.wait_group 0;")
__device__ __forceinline__ uint32_t h2u(float a, float b){
  __half2 h = __floats2half2_rn(a,b); return *(uint32_t*)&h;
}

// ---------------- fp32 -> fp16 convert ----------------
__global__ void f2h(const float4* __restrict__ in, __half2* __restrict__ out, int n4){
  int i = blockIdx.x*blockDim.x + threadIdx.x;
  if (i < n4){
    float4 v = in[i];
    out[2*i]   = __floats2half2_rn(v.x, v.y);
    out[2*i+1] = __floats2half2_rn(v.z, v.w);
  }
}

// ---------------------------------------------------------------------------
// GEMM body: Y[M,N] = X[M,K] @ W[N,K]^T + bias.  fp16 in, fp32 acc.
// 128x128x32 tiles, 8 warps (2x4), warp tile 64x32, cp.async 2-stage,
// ldmatrix fragments.  Smem stride 40 halves (80B) -> conflict-free ldsm +
// 16B-aligned cp.async chunks.
// ---------------------------------------------------------------------------
#define GST 40
#define GSTG_B (128*GST*2)

template<bool HOUT>
__device__ __forceinline__ void gemm_body(
    const __half* __restrict__ X, const __half* __restrict__ W,
    const float* __restrict__ bias, void* __restrict__ Yv,
    int M, int N, int K)
{
  __shared__ __half As[2][128*GST];
  __shared__ __half Bs[2][128*GST];
  const int tid = threadIdx.x;
  const int warp = tid >> 5, lane = tid & 31;
  const int wm = warp >> 2, wn = warp & 3;
  const int g = lane >> 2, q = lane & 3;
  const int bm = blockIdx.y * 128, bn = blockIdx.x * 128;

  const uint32_t as_base = (uint32_t)__cvta_generic_to_shared(&As[0][0]);
  const uint32_t bs_base = (uint32_t)__cvta_generic_to_shared(&Bs[0][0]);

  float acc[4][4][4];
  #pragma unroll
  for (int i=0;i<4;i++)
    #pragma unroll
    for (int j=0;j<4;j++){ acc[i][j][0]=0.f; acc[i][j][1]=0.f; acc[i][j][2]=0.f; acc[i][j][3]=0.f; }

  const int lrow = tid >> 2, lsub = tid & 3;   // 2 chunks per thread per tensor
  auto load_stage = [&](int s, int k0){
    #pragma unroll
    for (int i=0;i<2;i++){
      const int row = lrow + i*64;
      const uint32_t off = (uint32_t)(row*GST + lsub*8)*2 + s*GSTG_B;
      cp16(as_base + off, X + (bm+row)*K + k0 + lsub*8);
      cp16(bs_base + off, W + (bn+row)*K + k0 + lsub*8);
    }
    CP_COMMIT();
  };

  load_stage(0, 0);
  const int KT = K / 32;
  for (int kt=0; kt<KT; kt++){
    const int s = kt & 1;
    CP_WAIT0();
    __syncthreads();
    if (kt+1 < KT) load_stage(s^1, (kt+1)*32);

    #pragma unroll
    for (int ks=0; ks<2; ks++){
      uint32_t af[4][4];
      #pragma unroll
      for (int mt=0; mt<4; mt++){
        uint32_t ad = as_base + s*GSTG_B +
          (uint32_t)(((wm*64 + mt*16 + (lane&15))*GST + ks*16 + (lane>>4)*8) << 1);
        ldsm4(af[mt], ad);
      }
      #pragma unroll
      for (int p=0; p<2; p++){
        uint32_t bf[4];
        uint32_t bd = bs_base + s*GSTG_B +
          (uint32_t)(((wn*32 + p*16 + ((lane>>4)<<3) + (lane&7))*GST + ks*16 + ((lane>>3)&1)*8) << 1);
        ldsm4(bf, bd);
        #pragma unroll
        for (int mt=0; mt<4; mt++){
          mma16816(acc[mt][2*p],   af[mt], bf[0], bf[1]);
          mma16816(acc[mt][2*p+1], af[mt], bf[2], bf[3]);
        }
      }
    }
    __syncthreads();
  }

  #pragma unroll
  for (int mt=0; mt<4; mt++){
    const int r0 = bm + wm*64 + mt*16 + g;
    #pragma unroll
    for (int nt=0; nt<4; nt++){
      const int c = bn + wn*32 + nt*8 + 2*q;
      const float b0 = bias[c], b1 = bias[c+1];
      if (HOUT){
        __half* Y = (__half*)Yv;
        *(uint32_t*)&Y[r0*N + c]     = h2u(acc[mt][nt][0]+b0, acc[mt][nt][1]+b1);
        *(uint32_t*)&Y[(r0+8)*N + c] = h2u(acc[mt][nt][2]+b0, acc[mt][nt][3]+b1);
      } else {
        float* Y = (float*)Yv;
        *(float2*)&Y[r0*N + c]     = make_float2(acc[mt][nt][0]+b0, acc[mt][nt][1]+b1);
        *(float2*)&Y[(r0+8)*N + c] = make_float2(acc[mt][nt][2]+b0, acc[mt][nt][3]+b1);
      }
    }
  }
}

__global__ __launch_bounds__(256,2)
void proj3(const __half* x0, const __half* x1, const __half* x2,
           const __half* w0, const __half* w1, const __half* w2,
           const float* b0, const float* b1, const float* b2,
           __half* y0, __half* y1, __half* y2, int M, int N, int K){
  const __half* X[3] = {x0,x1,x2};
  const __half* W[3] = {w0,w1,w2};
  const float*  Bp[3] = {b0,b1,b2};
  __half* Y[3] = {y0,y1,y2};
  const int z = blockIdx.z;
  gemm_body<true>(X[z], W[z], Bp[z], Y[z], M, N, K);
}

__global__ __launch_bounds__(256,2)
void gemm_out(const __half* X, const __half* W, const float* bias,
              float* Y, int M, int N, int K){
  gemm_body<false>(X, W, bias, Y, M, N, K);
}

// ---------------------------------------------------------------------------
// Causal flash attention, fp16 mma + ldmatrix, P kept in registers.
// Block = 128 q rows x (b,h); 8 warps x 16 rows. K/V tiles double-buffered
// via cp.async, smem stride 72 halves (144B, conflict-free ldsm).
// ---------------------------------------------------------------------------
#define KVST  (128*72)            // halves per tensor per buffer
#define ABUF  (2*KVST)            // halves per buffer (K then V)
#define ATT_SMEM (2*ABUF*2)       // bytes (2 buffers)

__global__ __launch_bounds__(256,1)
void attn_f16(const __half* __restrict__ Q, const __half* __restrict__ K,
              const __half* __restrict__ V, __half* __restrict__ O){
  extern __shared__ __half sm[];
  const uint32_t smb = (uint32_t)__cvta_generic_to_shared(sm);

  const int tid = threadIdx.x, warp = tid >> 5, lane = tid & 31;
  const int g = lane >> 2, q = lane & 3;
  const int iq = blockIdx.x, bh = blockIdx.y;
  const int b = bh >> 4, h = bh & 15;
  const int base = b * S_ * D_;
  const int hcol = h * DK_;
  const int qb = iq * 128;
  const int row0 = qb + warp*16 + g;
  const int row1 = row0 + 8;

  // persistent Q fragments: 4 k16-tiles (DK=64)
  uint32_t qf[4][4];
  {
    const __half* q0 = Q + base + (size_t)row0*D_ + hcol;
    const __half* q1 = q0 + 8*D_;
    #pragma unroll
    for (int kt=0; kt<4; kt++){
      qf[kt][0] = *(const uint32_t*)(q0 + kt*16 + 2*q);
      qf[kt][1] = *(const uint32_t*)(q1 + kt*16 + 2*q);
      qf[kt][2] = *(const uint32_t*)(q0 + kt*16 + 2*q + 8);
      qf[kt][3] = *(const uint32_t*)(q1 + kt*16 + 2*q + 8);
    }
  }

  float oacc[8][4];
  #pragma unroll
  for (int i=0;i<8;i++){ oacc[i][0]=0.f; oacc[i][1]=0.f; oacc[i][2]=0.f; oacc[i][3]=0.f; }
  float m0=-1e30f, m1=-1e30f, l0=0.f, l1=0.f;
  const float SC = 0.1803368801111204f;   // log2(e)/sqrt(64)

  const int lrow = tid >> 3, lsub = tid & 7;   // 4 chunks per tensor per thread
  auto load_tile = [&](int buf, int kb){
    #pragma unroll
    for (int i=0;i<4;i++){
      const int row = lrow + i*32;
      const uint32_t off = (uint32_t)(buf*ABUF + row*72 + lsub*8)*2;
      cp16(smb + off,          K + base + (size_t)(kb+row)*D_ + hcol + lsub*8);
      cp16(smb + (KVST*2) + off, V + base + (size_t)(kb+row)*D_ + hcol + lsub*8);
    }
    CP_COMMIT();
  };

  load_tile(0, 0);
  for (int j=0; j<=iq; j++){
    const int buf = j & 1;
    CP_WAIT0();
    __syncthreads();
    if (j+1 <= iq) load_tile(buf^1, (j+1)*128);

    const uint32_t ksb = smb + (uint32_t)(buf*ABUF)*2;
    const uint32_t vsb = ksb + (uint32_t)(KVST)*2;

    // S = Q @ K^T  (m16 x n128 per warp)
    float s[16][4];
    #pragma unroll
    for (int nt=0;nt<16;nt++){ s[nt][0]=0.f; s[nt][1]=0.f; s[nt][2]=0.f; s[nt][3]=0.f; }
    #pragma unroll
    for (int kt=0; kt<4; kt++){
      #pragma unroll
      for (int p=0; p<8; p++){
        uint32_t bf[4];
        uint32_t ad = ksb + (uint32_t)(((p*16 + ((lane>>4)<<3) + (lane&7))*72
                                        + kt*16 + ((lane>>3)&1)*8) << 1);
        ldsm4(bf, ad);
        mma16816(s[2*p],   qf[kt], bf[0], bf[1]);
        mma16816(s[2*p+1], qf[kt], bf[2], bf[3]);
      }
    }

    // scale + causal mask (diagonal tile only) + row max
    const int kb = j*128;
    const bool diag = (j == iq);
    float mx0=-1e30f, mx1=-1e30f;
    #pragma unroll
    for (int nt=0; nt<16; nt++){
      const int c0 = kb + nt*8 + 2*q;
      float v0 = s[nt][0]*SC, v1 = s[nt][1]*SC, v2 = s[nt][2]*SC, v3 = s[nt][3]*SC;
      if (diag){
        if (c0   > row0) v0 = -1e30f;
        if (c0+1 > row0) v1 = -1e30f;
        if (c0   > row1) v2 = -1e30f;
        if (c0+1 > row1) v3 = -1e30f;
      }
      s[nt][0]=v0; s[nt][1]=v1; s[nt][2]=v2; s[nt][3]=v3;
      mx0 = fmaxf(mx0, fmaxf(v0,v1));
      mx1 = fmaxf(mx1, fmaxf(v2,v3));
    }
    mx0 = fmaxf(mx0, __shfl_xor_sync(0xffffffffu, mx0, 1));
    mx0 = fmaxf(mx0, __shfl_xor_sync(0xffffffffu, mx0, 2));
    mx1 = fmaxf(mx1, __shfl_xor_sync(0xffffffffu, mx1, 1));
    mx1 = fmaxf(mx1, __shfl_xor_sync(0xffffffffu, mx1, 2));
    const float mn0 = fmaxf(m0, mx0), mn1 = fmaxf(m1, mx1);
    const float a0 = exp2f(m0 - mn0), a1 = exp2f(m1 - mn1);
    m0 = mn0; m1 = mn1;
    #pragma unroll
    for (int nt=0; nt<8; nt++){
      oacc[nt][0]*=a0; oacc[nt][1]*=a0; oacc[nt][2]*=a1; oacc[nt][3]*=a1;
    }

    // exp -> P fragments in registers (C-layout == A-layout trick)
    uint32_t pa[8][4];
    float sum0=0.f, sum1=0.f;
    #pragma unroll
    for (int t=0; t<8; t++){
      float e00 = exp2f(s[2*t][0]-m0),   e01 = exp2f(s[2*t][1]-m0);
      float e02 = exp2f(s[2*t][2]-m1),   e03 = exp2f(s[2*t][3]-m1);
      float e10 = exp2f(s[2*t+1][0]-m0), e11 = exp2f(s[2*t+1][1]-m0);
      float e12 = exp2f(s[2*t+1][2]-m1), e13 = exp2f(s[2*t+1][3]-m1);
      sum0 += (e00+e01) + (e10+e11);
      sum1 += (e02+e03) + (e12+e13);
      pa[t][0] = h2u(e00,e01);
      pa[t][1] = h2u(e02,e03);
      pa[t][2] = h2u(e10,e11);
      pa[t][3] = h2u(e12,e13);
    }
    sum0 += __shfl_xor_sync(0xffffffffu, sum0, 1);
    sum0 += __shfl_xor_sync(0xffffffffu, sum0, 2);
    sum1 += __shfl_xor_sync(0xffffffffu, sum1, 1);
    sum1 += __shfl_xor_sync(0xffffffffu, sum1, 2);
    l0 = l0*a0 + sum0; l1 = l1*a1 + sum1;

    // O += P @ V   (k=128 keys, n=64 dims), V via ldmatrix.trans
    #pragma unroll
    for (int kt=0; kt<8; kt++){
      #pragma unroll
      for (int p=0; p<4; p++){
        uint32_t bf[4];
        uint32_t ad = vsb + (uint32_t)(((kt*16 + ((lane>>3)&1)*8 + (lane&7))*72
                                        + p*16 + ((lane>>4)<<3)) << 1);
        ldsm4t(bf, ad);
        mma16816(oacc[2*p],   pa[kt], bf[0], bf[1]);
        mma16816(oacc[2*p+1], pa[kt], bf[2], bf[3]);
      }
    }
  }

  const float i0 = 1.f/l0, i1 = 1.f/l1;
  __half* o0 = O + base + (size_t)row0*D_ + hcol;
  __half* o1 = O + base + (size_t)row1*D_ + hcol;
  #pragma unroll
  for (int nt=0; nt<8; nt++){
    const int c = nt*8 + 2*q;
    *(uint32_t*)&o0[c] = h2u(oacc[nt][0]*i0, oacc[nt][1]*i0);
    *(uint32_t*)&o1[c] = h2u(oacc[nt][2]*i1, oacc[nt][3]*i1);
  }
}

// ---------------------------------------------------------------------------
extern "C" void kernel_launch(void* const* d_in, const int* in_sizes, int n_in,
                              void* d_out, int out_size){
  const float* xq = (const float*)d_in[0];
  const float* xk = (const float*)d_in[1];
  const float* xv = (const float*)d_in[2];
  const float* Wq = (const float*)d_in[3];
  const float* bq = (const float*)d_in[4];
  const float* Wk = (const float*)d_in[5];
  const float* bk = (const float*)d_in[6];
  const float* Wv = (const float*)d_in[7];
  const float* bv = (const float*)d_in[8];
  const float* Wo = (const float*)d_in[9];
  const float* bo = (const float*)d_in[10];
  float* out = (float*)d_out;

  __half *hxq,*hxk,*hxv,*hwq,*hwk,*hwv,*hwo,*hQ,*hK,*hV,*hA;
  cudaGetSymbolAddress((void**)&hxq, g_xq);
  cudaGetSymbolAddress((void**)&hxk, g_xk);
  cudaGetSymbolAddress((void**)&hxv, g_xv);
  cudaGetSymbolAddress((void**)&hwq, g_wq);
  cudaGetSymbolAddress((void**)&hwk, g_wk);
  cudaGetSymbolAddress((void**)&hwv, g_wv);
  cudaGetSymbolAddress((void**)&hwo, g_wo);
  cudaGetSymbolAddress((void**)&hQ, g_Q);
  cudaGetSymbolAddress((void**)&hK, g_K);
  cudaGetSymbolAddress((void**)&hV, g_V);
  cudaGetSymbolAddress((void**)&hA, g_A);

  cudaFuncSetAttribute(attn_f16, cudaFuncAttributeMaxDynamicSharedMemorySize, ATT_SMEM);

  const int NX4 = MTOT*D_/4;   // 2,097,152
  const int NW4 = D_*D_/4;     // 262,144
  f2h<<<NX4/256, 256>>>((const float4*)xq, (__half2*)hxq, NX4);
  f2h<<<NX4/256, 256>>>((const float4*)xk, (__half2*)hxk, NX4);
  f2h<<<NX4/256, 256>>>((const float4*)xv, (__half2*)hxv, NX4);
  f2h<<<NW4/256, 256>>>((const float4*)Wq, (__half2*)hwq, NW4);
  f2h<<<NW4/256, 256>>>((const float4*)Wk, (__half2*)hwk, NW4);
  f2h<<<NW4/256, 256>>>((const float4*)Wv, (__half2*)hwv, NW4);
  f2h<<<NW4/256, 256>>>((const float4*)Wo, (__half2*)hwo, NW4);

  proj3<<<dim3(D_/128, MTOT/128, 3), 256>>>(hxq,hxk,hxv, hwq,hwk,hwv,
                                            bq,bk,bv, hQ,hK,hV, MTOT, D_, D_);
  attn_f16<<<dim3(S_/128, B_*H_), 256, ATT_SMEM>>>(hQ, hK, hV, hA);
  gemm_out<<<dim3(D_/128, MTOT/128), 256>>>(hA, hwo, bo, out, MTOT, D_, D_);
}

// round 4
// speedup vs baseline: 2.5126x; 1.1213x over previous
#include <cuda_runtime.h>
#include <cuda_fp16.h>
#include <stdint.h>

#define B_ 4
#define S_ 2048
#define D_ 1024
#define H_ 16
#define DK_ 64
#define MTOT (B_*S_)

// log2(e)/sqrt(DK): folded into Wq/bq so attention scores come out pre-scaled
#define SC_LOG2E 0.1803368801111204f

// fp16 staging buffers (device globals: allocation-free rule)
__device__ __half g_xq[MTOT*D_];
__device__ __half g_xk[MTOT*D_];
__device__ __half g_xv[MTOT*D_];
__device__ __half g_wq[D_*D_];
__device__ __half g_wk[D_*D_];
__device__ __half g_wv[D_*D_];
__device__ __half g_wo[D_*D_];
__device__ __half g_Q[MTOT*D_];
__device__ __half g_K[MTOT*D_];
__device__ __half g_V[MTOT*D_];
__device__ __half g_A[MTOT*D_];

// ---------------- PTX helpers ----------------
__device__ __forceinline__ float ex2f(float x){
  float r; asm("ex2.approx.ftz.f32 %0, %1;" : "=f"(r) : "f"(x)); return r;
}
__device__ __forceinline__ void ldsm4(uint32_t* r, uint32_t a){
  asm volatile("ldmatrix.sync.aligned.m8n8.x4.shared.b16 {%0,%1,%2,%3},[%4];"
    : "=r"(r[0]),"=r"(r[1]),"=r"(r[2]),"=r"(r[3]) : "r"(a));
}
__device__ __forceinline__ void ldsm4t(uint32_t* r, uint32_t a){
  asm volatile("ldmatrix.sync.aligned.m8n8.x4.trans.shared.b16 {%0,%1,%2,%3},[%4];"
    : "=r"(r[0]),"=r"(r[1]),"=r"(r[2]),"=r"(r[3]) : "r"(a));
}
__device__ __forceinline__ void mma16816(float* c, const uint32_t* a, uint32_t b0, uint32_t b1){
  asm volatile("mma.sync.aligned.m16n8k16.row.col.f32.f16.f16.f32 "
    "{%0,%1,%2,%3},{%4,%5,%6,%7},{%8,%9},{%0,%1,%2,%3};"
    : "+f"(c[0]),"+f"(c[1]),"+f"(c[2]),"+f"(c[3])
    : "r"(a[0]),"r"(a[1]),"r"(a[2]),"r"(a[3]),"r"(b0),"r"(b1));
}
__device__ __forceinline__ void cp16(uint32_t d, const void* s){
  asm volatile("cp.async.cg.shared.global [%0],[%1],16;" :: "r"(d),"l"(s));
}
#define CP_COMMIT() asm volatile("cp.async.commit_group;")
#define CP_WAIT0()  asm volatile("cp.async.wait_group 0;")
__device__ __forceinline__ uint32_t h2u(float a, float b){
  __half2 h = __floats2half2_rn(a,b); return *(uint32_t*)&h;
}

// ---------------- fused fp32 -> fp16 conversion ----------------
// One 16B load -> one 8B store per step, ITER compile-time unrolled for MLP.
template<int ITER>
__global__ void f2h_act(const float4* __restrict__ a0, const float4* __restrict__ a1,
                        const float4* __restrict__ a2,
                        uint2* __restrict__ o0, uint2* __restrict__ o1, uint2* __restrict__ o2){
  const float4* in; uint2* out;
  if (blockIdx.z == 0){ in=a0; out=o0; }
  else if (blockIdx.z == 1){ in=a1; out=o1; }
  else { in=a2; out=o2; }
  const int t = blockIdx.x*blockDim.x + threadIdx.x;
  const int stride = gridDim.x*blockDim.x;
  #pragma unroll
  for (int k=0;k<ITER;k++){
    const int i = t + k*stride;
    float4 v = in[i];
    uint2 u; u.x = h2u(v.x,v.y); u.y = h2u(v.z,v.w);
    out[i] = u;
  }
}

template<int ITER>
__global__ void f2h_w(const float4* __restrict__ a0, const float4* __restrict__ a1,
                      const float4* __restrict__ a2, const float4* __restrict__ a3,
                      uint2* __restrict__ o0, uint2* __restrict__ o1,
                      uint2* __restrict__ o2, uint2* __restrict__ o3, float s0){
  const float4* in; uint2* out; float sc = 1.f;
  if (blockIdx.z == 0){ in=a0; out=o0; sc=s0; }
  else if (blockIdx.z == 1){ in=a1; out=o1; }
  else if (blockIdx.z == 2){ in=a2; out=o2; }
  else { in=a3; out=o3; }
  const int t = blockIdx.x*blockDim.x + threadIdx.x;
  const int stride = gridDim.x*blockDim.x;
  #pragma unroll
  for (int k=0;k<ITER;k++){
    const int i = t + k*stride;
    float4 v = in[i];
    uint2 u; u.x = h2u(v.x*sc, v.y*sc); u.y = h2u(v.z*sc, v.w*sc);
    out[i] = u;
  }
}

// ---------------------------------------------------------------------------
// GEMM body: Y[M,N] = X[M,K] @ W[N,K]^T + bias*bscale.  fp16 in, fp32 acc.
// 128x128x32 tiles, 8 warps (2x4), warp tile 64x32, cp.async 2-stage,
// ldmatrix fragments.  Smem stride 40 halves -> conflict-free ldsm.
// ---------------------------------------------------------------------------
#define GST 40
#define GSTG_B (128*GST*2)

template<bool HOUT>
__device__ __forceinline__ void gemm_body(
    const __half* __restrict__ X, const __half* __restrict__ W,
    const float* __restrict__ bias, float bscale, void* __restrict__ Yv,
    int M, int N, int K)
{
  __shared__ __half As[2][128*GST];
  __shared__ __half Bs[2][128*GST];
  const int tid = threadIdx.x;
  const int warp = tid >> 5, lane = tid & 31;
  const int wm = warp >> 2, wn = warp & 3;
  const int g = lane >> 2, q = lane & 3;
  const int bm = blockIdx.y * 128, bn = blockIdx.x * 128;

  const uint32_t as_base = (uint32_t)__cvta_generic_to_shared(&As[0][0]);
  const uint32_t bs_base = (uint32_t)__cvta_generic_to_shared(&Bs[0][0]);

  float acc[4][4][4];
  #pragma unroll
  for (int i=0;i<4;i++)
    #pragma unroll
    for (int j=0;j<4;j++){ acc[i][j][0]=0.f; acc[i][j][1]=0.f; acc[i][j][2]=0.f; acc[i][j][3]=0.f; }

  const int lrow = tid >> 2, lsub = tid & 3;
  auto load_stage = [&](int s, int k0){
    #pragma unroll
    for (int i=0;i<2;i++){
      const int row = lrow + i*64;
      const uint32_t off = (uint32_t)(row*GST + lsub*8)*2 + s*GSTG_B;
      cp16(as_base + off, X + (bm+row)*K + k0 + lsub*8);
      cp16(bs_base + off, W + (bn+row)*K + k0 + lsub*8);
    }
    CP_COMMIT();
  };

  load_stage(0, 0);
  const int KT = K / 32;
  for (int kt=0; kt<KT; kt++){
    const int s = kt & 1;
    CP_WAIT0();
    __syncthreads();
    if (kt+1 < KT) load_stage(s^1, (kt+1)*32);

    #pragma unroll
    for (int ks=0; ks<2; ks++){
      uint32_t af[4][4];
      #pragma unroll
      for (int mt=0; mt<4; mt++){
        uint32_t ad = as_base + s*GSTG_B +
          (uint32_t)(((wm*64 + mt*16 + (lane&15))*GST + ks*16 + (lane>>4)*8) << 1);
        ldsm4(af[mt], ad);
      }
      #pragma unroll
      for (int p=0; p<2; p++){
        uint32_t bf[4];
        uint32_t bd = bs_base + s*GSTG_B +
          (uint32_t)(((wn*32 + p*16 + ((lane>>4)<<3) + (lane&7))*GST + ks*16 + ((lane>>3)&1)*8) << 1);
        ldsm4(bf, bd);
        #pragma unroll
        for (int mt=0; mt<4; mt++){
          mma16816(acc[mt][2*p],   af[mt], bf[0], bf[1]);
          mma16816(acc[mt][2*p+1], af[mt], bf[2], bf[3]);
        }
      }
    }
    __syncthreads();
  }

  #pragma unroll
  for (int mt=0; mt<4; mt++){
    const int r0 = bm + wm*64 + mt*16 + g;
    #pragma unroll
    for (int nt=0; nt<4; nt++){
      const int c = bn + wn*32 + nt*8 + 2*q;
      const float b0 = bias[c]*bscale, b1 = bias[c+1]*bscale;
      if (HOUT){
        __half* Y = (__half*)Yv;
        *(uint32_t*)&Y[r0*N + c]     = h2u(acc[mt][nt][0]+b0, acc[mt][nt][1]+b1);
        *(uint32_t*)&Y[(r0+8)*N + c] = h2u(acc[mt][nt][2]+b0, acc[mt][nt][3]+b1);
      } else {
        float* Y = (float*)Yv;
        *(float2*)&Y[r0*N + c]     = make_float2(acc[mt][nt][0]+b0, acc[mt][nt][1]+b1);
        *(float2*)&Y[(r0+8)*N + c] = make_float2(acc[mt][nt][2]+b0, acc[mt][nt][3]+b1);
      }
    }
  }
}

__global__ __launch_bounds__(256,2)
void proj3(const __half* x0, const __half* x1, const __half* x2,
           const __half* w0, const __half* w1, const __half* w2,
           const float* b0, const float* b1, const float* b2,
           __half* y0, __half* y1, __half* y2, int M, int N, int K){
  const __half* X[3] = {x0,x1,x2};
  const __half* W[3] = {w0,w1,w2};
  const float*  Bp[3] = {b0,b1,b2};
  __half* Y[3] = {y0,y1,y2};
  const int z = blockIdx.z;
  const float bs = (z == 0) ? SC_LOG2E : 1.f;   // Wq/bq carry softmax scale
  gemm_body<true>(X[z], W[z], Bp[z], bs, Y[z], M, N, K);
}

__global__ __launch_bounds__(256,2)
void gemm_out(const __half* X, const __half* W, const float* bias,
              float* Y, int M, int N, int K){
  gemm_body<false>(X, W, bias, 1.f, Y, M, N, K);
}

// ---------------------------------------------------------------------------
// Causal flash attention, fp16 mma + ldmatrix, P in registers.
// grid = (bh, iq-reversed): heaviest q-tiles scheduled first.
// Scores arrive pre-scaled by log2(e)/sqrt(dk) (folded into Wq).
// ---------------------------------------------------------------------------
#define KVST  (128*72)
#define ABUF  (2*KVST)
#define ATT_SMEM (2*ABUF*2)

__global__ __launch_bounds__(256,1)
void attn_f16(const __half* __restrict__ Q, const __half* __restrict__ K,
              const __half* __restrict__ V, __half* __restrict__ O){
  extern __shared__ __half sm[];
  const uint32_t smb = (uint32_t)__cvta_generic_to_shared(sm);

  const int tid = threadIdx.x, warp = tid >> 5, lane = tid & 31;
  const int g = lane >> 2, q = lane & 3;
  const int bh = blockIdx.x;
  const int iq = gridDim.y - 1 - blockIdx.y;      // heavy tiles first
  const int b = bh >> 4, h = bh & 15;
  const int base = b * S_ * D_;
  const int hcol = h * DK_;
  const int qb = iq * 128;
  const int row0 = qb + warp*16 + g;
  const int row1 = row0 + 8;

  // persistent Q fragments: 4 k16-tiles (DK=64)
  uint32_t qf[4][4];
  {
    const __half* q0 = Q + base + (size_t)row0*D_ + hcol;
    const __half* q1 = q0 + 8*D_;
    #pragma unroll
    for (int kt=0; kt<4; kt++){
      qf[kt][0] = *(const uint32_t*)(q0 + kt*16 + 2*q);
      qf[kt][1] = *(const uint32_t*)(q1 + kt*16 + 2*q);
      qf[kt][2] = *(const uint32_t*)(q0 + kt*16 + 2*q + 8);
      qf[kt][3] = *(const uint32_t*)(q1 + kt*16 + 2*q + 8);
    }
  }

  float oacc[8][4];
  #pragma unroll
  for (int i=0;i<8;i++){ oacc[i][0]=0.f; oacc[i][1]=0.f; oacc[i][2]=0.f; oacc[i][3]=0.f; }
  float m0=-1e30f, m1=-1e30f, l0=0.f, l1=0.f;

  const int lrow = tid >> 3, lsub = tid & 7;
  auto load_tile = [&](int buf, int kb){
    #pragma unroll
    for (int i=0;i<4;i++){
      const int row = lrow + i*32;
      const uint32_t off = (uint32_t)(buf*ABUF + row*72 + lsub*8)*2;
      cp16(smb + off,            K + base + (size_t)(kb+row)*D_ + hcol + lsub*8);
      cp16(smb + (KVST*2) + off, V + base + (size_t)(kb+row)*D_ + hcol + lsub*8);
    }
    CP_COMMIT();
  };

  load_tile(0, 0);
  for (int j=0; j<=iq; j++){
    const int buf = j & 1;
    CP_WAIT0();
    __syncthreads();
    if (j+1 <= iq) load_tile(buf^1, (j+1)*128);

    const uint32_t ksb = smb + (uint32_t)(buf*ABUF)*2;
    const uint32_t vsb = ksb + (uint32_t)(KVST)*2;

    // S = Q @ K^T  (m16 x n128 per warp), already log2e/sqrt(dk) scaled
    float s[16][4];
    #pragma unroll
    for (int nt=0;nt<16;nt++){ s[nt][0]=0.f; s[nt][1]=0.f; s[nt][2]=0.f; s[nt][3]=0.f; }
    #pragma unroll
    for (int kt=0; kt<4; kt++){
      #pragma unroll
      for (int p=0; p<8; p++){
        uint32_t bf[4];
        uint32_t ad = ksb + (uint32_t)(((p*16 + ((lane>>4)<<3) + (lane&7))*72
                                        + kt*16 + ((lane>>3)&1)*8) << 1);
        ldsm4(bf, ad);
        mma16816(s[2*p],   qf[kt], bf[0], bf[1]);
        mma16816(s[2*p+1], qf[kt], bf[2], bf[3]);
      }
    }

    // causal mask (diagonal tile only) + row max
    const int kb = j*128;
    const bool diag = (j == iq);
    float mx0=-1e30f, mx1=-1e30f;
    #pragma unroll
    for (int nt=0; nt<16; nt++){
      const int c0 = kb + nt*8 + 2*q;
      float v0 = s[nt][0], v1 = s[nt][1], v2 = s[nt][2], v3 = s[nt][3];
      if (diag){
        if (c0   > row0) v0 = -1e30f;
        if (c0+1 > row0) v1 = -1e30f;
        if (c0   > row1) v2 = -1e30f;
        if (c0+1 > row1) v3 = -1e30f;
        s[nt][0]=v0; s[nt][1]=v1; s[nt][2]=v2; s[nt][3]=v3;
      }
      mx0 = fmaxf(mx0, fmaxf(v0,v1));
      mx1 = fmaxf(mx1, fmaxf(v2,v3));
    }
    mx0 = fmaxf(mx0, __shfl_xor_sync(0xffffffffu, mx0, 1));
    mx0 = fmaxf(mx0, __shfl_xor_sync(0xffffffffu, mx0, 2));
    mx1 = fmaxf(mx1, __shfl_xor_sync(0xffffffffu, mx1, 1));
    mx1 = fmaxf(mx1, __shfl_xor_sync(0xffffffffu, mx1, 2));
    const float mn0 = fmaxf(m0, mx0), mn1 = fmaxf(m1, mx1);
    const float a0 = ex2f(m0 - mn0), a1 = ex2f(m1 - mn1);
    m0 = mn0; m1 = mn1;
    #pragma unroll
    for (int nt=0; nt<8; nt++){
      oacc[nt][0]*=a0; oacc[nt][1]*=a0; oacc[nt][2]*=a1; oacc[nt][3]*=a1;
    }

    // exp -> P fragments in registers (C-layout == A-layout)
    uint32_t pa[8][4];
    float sum0=0.f, sum1=0.f;
    #pragma unroll
    for (int t=0; t<8; t++){
      float e00 = ex2f(s[2*t][0]-m0),   e01 = ex2f(s[2*t][1]-m0);
      float e02 = ex2f(s[2*t][2]-m1),   e03 = ex2f(s[2*t][3]-m1);
      float e10 = ex2f(s[2*t+1][0]-m0), e11 = ex2f(s[2*t+1][1]-m0);
      float e12 = ex2f(s[2*t+1][2]-m1), e13 = ex2f(s[2*t+1][3]-m1);
      sum0 += (e00+e01) + (e10+e11);
      sum1 += (e02+e03) + (e12+e13);
      pa[t][0] = h2u(e00,e01);
      pa[t][1] = h2u(e02,e03);
      pa[t][2] = h2u(e10,e11);
      pa[t][3] = h2u(e12,e13);
    }
    sum0 += __shfl_xor_sync(0xffffffffu, sum0, 1);
    sum0 += __shfl_xor_sync(0xffffffffu, sum0, 2);
    sum1 += __shfl_xor_sync(0xffffffffu, sum1, 1);
    sum1 += __shfl_xor_sync(0xffffffffu, sum1, 2);
    l0 = l0*a0 + sum0; l1 = l1*a1 + sum1;

    // O += P @ V   (k=128 keys, n=64 dims), V via ldmatrix.trans
    #pragma unroll
    for (int kt=0; kt<8; kt++){
      #pragma unroll
      for (int p=0; p<4; p++){
        uint32_t bf[4];
        uint32_t ad = vsb + (uint32_t)(((kt*16 + ((lane>>3)&1)*8 + (lane&7))*72
                                        + p*16 + ((lane>>4)<<3)) << 1);
        ldsm4t(bf, ad);
        mma16816(oacc[2*p],   pa[kt], bf[0], bf[1]);
        mma16816(oacc[2*p+1], pa[kt], bf[2], bf[3]);
      }
    }
  }

  const float i0 = 1.f/l0, i1 = 1.f/l1;
  __half* o0 = O + base + (size_t)row0*D_ + hcol;
  __half* o1 = O + base + (size_t)row1*D_ + hcol;
  #pragma unroll
  for (int nt=0; nt<8; nt++){
    const int c = nt*8 + 2*q;
    *(uint32_t*)&o0[c] = h2u(oacc[nt][0]*i0, oacc[nt][1]*i0);
    *(uint32_t*)&o1[c] = h2u(oacc[nt][2]*i1, oacc[nt][3]*i1);
  }
}

// ---------------------------------------------------------------------------
extern "C" void kernel_launch(void* const* d_in, const int* in_sizes, int n_in,
                              void* d_out, int out_size){
  const float* xq = (const float*)d_in[0];
  const float* xk = (const float*)d_in[1];
  const float* xv = (const float*)d_in[2];
  const float* Wq = (const float*)d_in[3];
  const float* bq = (const float*)d_in[4];
  const float* Wk = (const float*)d_in[5];
  const float* bk = (const float*)d_in[6];
  const float* Wv = (const float*)d_in[7];
  const float* bv = (const float*)d_in[8];
  const float* Wo = (const float*)d_in[9];
  const float* bo = (const float*)d_in[10];
  float* out = (float*)d_out;

  __half *hxq,*hxk,*hxv,*hwq,*hwk,*hwv,*hwo,*hQ,*hK,*hV,*hA;
  cudaGetSymbolAddress((void**)&hxq, g_xq);
  cudaGetSymbolAddress((void**)&hxk, g_xk);
  cudaGetSymbolAddress((void**)&hxv, g_xv);
  cudaGetSymbolAddress((void**)&hwq, g_wq);
  cudaGetSymbolAddress((void**)&hwk, g_wk);
  cudaGetSymbolAddress((void**)&hwv, g_wv);
  cudaGetSymbolAddress((void**)&hwo, g_wo);
  cudaGetSymbolAddress((void**)&hQ, g_Q);
  cudaGetSymbolAddress((void**)&hK, g_K);
  cudaGetSymbolAddress((void**)&hV, g_V);
  cudaGetSymbolAddress((void**)&hA, g_A);

  cudaFuncSetAttribute(attn_f16, cudaFuncAttributeMaxDynamicSharedMemorySize, ATT_SMEM);

  // activations: 3 x 2M float4 -> grid 2048x256 threads x 4 iters
  f2h_act<4><<<dim3(2048,1,3), 256>>>(
      (const float4*)xq, (const float4*)xk, (const float4*)xv,
      (uint2*)hxq, (uint2*)hxk, (uint2*)hxv);
  // weights: 4 x 256K float4 -> grid 256x256 threads x 4 iters; Wq carries scale
  f2h_w<4><<<dim3(256,1,4), 256>>>(
      (const float4*)Wq, (const float4*)Wk, (const float4*)Wv, (const float4*)Wo,
      (uint2*)hwq, (uint2*)hwk, (uint2*)hwv, (uint2*)hwo, SC_LOG2E);

  proj3<<<dim3(D_/128, MTOT/128, 3), 256>>>(hxq,hxk,hxv, hwq,hwk,hwv,
                                            bq,bk,bv, hQ,hK,hV, MTOT, D_, D_);
  attn_f16<<<dim3(B_*H_, S_/128), 256, ATT_SMEM>>>(hQ, hK, hV, hA);
  gemm_out<<<dim3(D_/128, MTOT/128), 256>>>(hA, hwo, bo, out, MTOT, D_, D_);
}